// round 10
// baseline (speedup 1.0000x reference)
#include <cuda_runtime.h>
#include <math.h>
#include <stdint.h>

typedef unsigned long long ull;

// Problem constants
#define B_    32
#define T_    128
#define V_    16000
#define E_    512
#define Z_    128
#define H_    1024
#define DIN_  640        // E+Z
#define ROWS_ 64         // 32 sample-pass rows + 32 teacher-forced rows
#define NBCL_ 500        // 16000/32 logits col tiles
#define TINYF 1.17549435e-38f

// Output layout (float32): [s_s (B*T)] [p_s (B*T*V)] [s_f (B*T)] [p_f (B*T*V)]
#define O_PS  4096
#define O_SF  65540096
#define O_PF  65544192

// ---------------- device scratch (static globals; no allocations) -------------
__device__ float d_A0T[(DIN_+H_)*ROWS_];    // [k][64r]; emb rows, z rows, h0^T
__device__ float d_h1T[H_*ROWS_];
__device__ float d_c0[ROWS_*H_];
__device__ float d_c1[ROWS_*H_];
__device__ float d_gp[16][ROWS_*4*H_];      // K-split gate partials
__device__ int   d_tok[B_];
__device__ float d_logits[ROWS_*V_];
__device__ float d_pmax[ROWS_*NBCL_];
__device__ float d_psum[ROWS_*NBCL_];
__device__ float d_rM[ROWS_];
__device__ float d_rL[ROWS_];
__device__ float d_amv [ROWS_*NBCL_];
__device__ int   d_ami [ROWS_*NBCL_];

// ---------------- f32x2 packed math helpers ------------------------------------
__device__ __forceinline__ ull pk2(float x){
  ull r; asm("mov.b64 %0,{%1,%1};" : "=l"(r) : "f"(x)); return r;
}
__device__ __forceinline__ void fma2(ull &d, ull a, ull b){
  asm("fma.rn.f32x2 %0, %1, %2, %0;" : "+l"(d) : "l"(a), "l"(b));
}
__device__ __forceinline__ float2 up2(ull v){
  float2 f; asm("mov.b64 {%0,%1},%2;" : "=f"(f.x), "=f"(f.y) : "l"(v)); return f;
}

// ---------------- cp.async helpers (logits only; .cg = L2-only) ----------------
__device__ __forceinline__ unsigned su32(const void* p){
  return (unsigned)__cvta_generic_to_shared(p);
}
__device__ __forceinline__ void cpa16(unsigned s, const void* g){
  asm volatile("cp.async.cg.shared.global [%0], [%1], 16;" :: "r"(s), "l"(g));
}
__device__ __forceinline__ void cp_commit(){ asm volatile("cp.async.commit_group;"); }
__device__ __forceinline__ void cp_wait3(){ asm volatile("cp.async.wait_group 3;"); }
__device__ __forceinline__ void cp_wait2(){ asm volatile("cp.async.wait_group 2;"); }
__device__ __forceinline__ void cp_wait1(){ asm volatile("cp.async.wait_group 1;"); }
__device__ __forceinline__ void cp_wait0(){ asm volatile("cp.async.wait_group 0;"); }

// ---------------- XLA-exact tanh (Eigen-style rational) ------------------------
__device__ __forceinline__ float tanh_xla(float x){
  float ax = fabsf(x);
  if (ax < 0.0004f) return x;
  float xc = fminf(fmaxf(x, -7.90531110763549805f), 7.90531110763549805f);
  float x2 = xc*xc;
  float p = fmaf(x2, -2.76076847742355e-16f, 2.00018790482477e-13f);
  p = fmaf(x2, p, -8.60467152213735e-11f);
  p = fmaf(x2, p,  5.12229709037114e-08f);
  p = fmaf(x2, p,  1.48572235717979e-05f);
  p = fmaf(x2, p,  6.37261928875436e-04f);
  p = fmaf(x2, p,  4.89352455891786e-03f);
  p = xc * p;
  float q = fmaf(x2, 1.19825839466702e-06f, 1.18534705686654e-04f);
  q = fmaf(x2, q, 2.26843463243900e-03f);
  q = fmaf(x2, q, 4.89352518554385e-03f);
  return p / q;
}
__device__ __forceinline__ float sigmoid_(float x){ return 0.5f + 0.5f*tanh_xla(0.5f*x); }

// ---------------- threefry2x32 (JAX partitionable) ----------------------------
__device__ __forceinline__ void tf2x32(unsigned k0, unsigned k1, unsigned x0, unsigned x1,
                                       unsigned &o0, unsigned &o1){
  unsigned k2 = k0 ^ k1 ^ 0x1BD11BDAu;
  x0 += k0; x1 += k1;
#define TFR(r) { x0 += x1; x1 = (x1<<(r)) | (x1>>(32-(r))); x1 ^= x0; }
  TFR(13) TFR(15) TFR(26) TFR(6)
  x0 += k1; x1 += k2 + 1u;
  TFR(17) TFR(29) TFR(16) TFR(24)
  x0 += k2; x1 += k0 + 2u;
  TFR(13) TFR(15) TFR(26) TFR(6)
  x0 += k0; x1 += k1 + 3u;
  TFR(17) TFR(29) TFR(16) TFR(24)
  x0 += k1; x1 += k2 + 4u;
  TFR(13) TFR(15) TFR(26) TFR(6)
  x0 += k2; x1 += k0 + 5u;
#undef TFR
  o0 = x0; o1 = x1;
}
__device__ __forceinline__ unsigned pbits(unsigned k0, unsigned k1, unsigned j){
  unsigned o0, o1; tf2x32(k0, k1, 0u, j, o0, o1); return o0 ^ o1;
}
__device__ __forceinline__ float gumbel_from_bits(unsigned bits){
  float f = __uint_as_float((bits>>9) | 0x3f800000u) - 1.0f;
  float u = fmaxf(TINYF, f + TINYF);
  return -logf(-logf(u));
}

// ---------------- init ---------------------------------------------------------
__global__ void k_init(const float* __restrict__ z, const float* __restrict__ emb){
  int i = blockIdx.x*blockDim.x + threadIdx.x;
  if (i < ROWS_*H_){
    d_A0T[DIN_*ROWS_ + i] = 0.f;    // h0^T = 0
    d_h1T[i] = 0.f;
    d_c0[i] = 0.f; d_c1[i] = 0.f;
  }
  if (i < Z_*ROWS_){                // z rows of A0T (constant across steps)
    int zz = i >> 6, r = i & 63;
    d_A0T[(E_+zz)*ROWS_ + r] = z[(r&31)*Z_ + zz];
  }
  if (i < E_*ROWS_){                // initial emb gather: START token (=1)
    int k = i >> 6, r = i & 63;
    d_A0T[(size_t)k*ROWS_ + r] = emb[(size_t)E_ + k];
  }
  if (i < B_) d_tok[i] = 1;
}

// ---- K-split GEMM (round-6 best): [64 x K]^T A @ [K x 4096] W, f32x2 ----------
// grid = 64 col-tiles x NSPLIT; block 128; each split = 4 chunks of 32 k-rows.
// Register-staged double buffer (best measured: 26.4us, fma 51%).
__global__ void __launch_bounds__(128) k_gemm(
    const float* __restrict__ A1, int alen1, const float* __restrict__ A2,
    const float* __restrict__ W1, int wlen1, const float* __restrict__ W2,
    float* __restrict__ gp)
{
  __shared__ float As[2][32*64];
  __shared__ float Ws[2][32*64];
  const int tid = threadIdx.x;
  const int ct = blockIdx.x & 63, sp = blockIdx.x >> 6;
  const int rg = tid >> 4, cg = tid & 15;
  const int kbeg = sp * 128;
  const int nch = 4;
  const int cbase = ct * 64;

  ull acc[8][2];
#pragma unroll
  for (int j=0;j<8;j++){ acc[j][0]=0ull; acc[j][1]=0ull; }

  float4 ra[4], rw[4];
  {
    int k0 = kbeg;
    const float* ap = (k0 < alen1) ? (A1 + (size_t)k0*64) : (A2 + (size_t)(k0-alen1)*64);
    const float* wp = (k0 < wlen1) ? (W1 + (size_t)k0*4096) : (W2 + (size_t)(k0-wlen1)*4096);
#pragma unroll
    for (int i=0;i<4;i++){
      int f = i*128 + tid;
      ra[i] = ((const float4*)ap)[f];
      int kk = f >> 4, c4 = (f & 15) * 4;
      rw[i] = *(const float4*)(wp + (size_t)kk*4096 + cbase + c4);
    }
  }
#pragma unroll
  for (int i=0;i<4;i++){
    int f = i*128 + tid, kk = f >> 4, c4 = (f & 15)*4;
    *(float4*)&As[0][kk*64 + c4] = ra[i];
    *(float4*)&Ws[0][kk*64 + c4] = rw[i];
  }
  __syncthreads();

#pragma unroll
  for (int ci = 0; ci < nch; ci++){
    if (ci+1 < nch){
      int k0 = kbeg + (ci+1)*32;
      const float* ap = (k0 < alen1) ? (A1 + (size_t)k0*64) : (A2 + (size_t)(k0-alen1)*64);
      const float* wp = (k0 < wlen1) ? (W1 + (size_t)k0*4096) : (W2 + (size_t)(k0-wlen1)*4096);
#pragma unroll
      for (int i=0;i<4;i++){
        int f = i*128 + tid;
        ra[i] = ((const float4*)ap)[f];
        int kk = f >> 4, c4 = (f & 15) * 4;
        rw[i] = *(const float4*)(wp + (size_t)kk*4096 + cbase + c4);
      }
    }
    const float* Ac = &As[ci&1][0];
    const float* Wc = &Ws[ci&1][0];
#pragma unroll
    for (int kk=0; kk<32; kk++){
      float4 a0 = *(const float4*)(Ac + kk*64 + rg*8);
      float4 a1 = *(const float4*)(Ac + kk*64 + rg*8 + 4);
      ulonglong2 w = *(const ulonglong2*)(Wc + kk*64 + cg*4);
      ull pa;
      pa = pk2(a0.x); fma2(acc[0][0],pa,w.x); fma2(acc[0][1],pa,w.y);
      pa = pk2(a0.y); fma2(acc[1][0],pa,w.x); fma2(acc[1][1],pa,w.y);
      pa = pk2(a0.z); fma2(acc[2][0],pa,w.x); fma2(acc[2][1],pa,w.y);
      pa = pk2(a0.w); fma2(acc[3][0],pa,w.x); fma2(acc[3][1],pa,w.y);
      pa = pk2(a1.x); fma2(acc[4][0],pa,w.x); fma2(acc[4][1],pa,w.y);
      pa = pk2(a1.y); fma2(acc[5][0],pa,w.x); fma2(acc[5][1],pa,w.y);
      pa = pk2(a1.z); fma2(acc[6][0],pa,w.x); fma2(acc[6][1],pa,w.y);
      pa = pk2(a1.w); fma2(acc[7][0],pa,w.x); fma2(acc[7][1],pa,w.y);
    }
    __syncthreads();
    if (ci+1 < nch){
      int nb = (ci+1)&1;
#pragma unroll
      for (int i=0;i<4;i++){
        int f = i*128 + tid, kk = f >> 4, c4 = (f & 15)*4;
        *(float4*)&As[nb][kk*64 + c4] = ra[i];
        *(float4*)&Ws[nb][kk*64 + c4] = rw[i];
      }
      __syncthreads();
    }
  }

  float* op = gp + (size_t)sp*ROWS_*4096;
#pragma unroll
  for (int j=0;j<8;j++){
    int r = rg*8 + j;
    float2 p0 = up2(acc[j][0]), p1 = up2(acc[j][1]);
    *(float4*)(op + (size_t)r*4096 + cbase + cg*4) = make_float4(p0.x,p0.y,p1.x,p1.y);
  }
}

// ---------------- bias + LSTM activation (float4); writes h^T ------------------
// grid 32 x 512; each thread: 4 consecutive h of one row. Same add order/element.
__global__ void __launch_bounds__(512) k_act(int nsplit, const float* __restrict__ b,
    float* __restrict__ c, float* __restrict__ hT)
{
  int idx = blockIdx.x*512 + threadIdx.x;      // 0..16383
  int h4 = (idx & 255) * 4, r = idx >> 8;
  size_t base = (size_t)r*4096;
  float4 gi = *(const float4*)(b + h4);
  float4 gf = *(const float4*)(b + 1024 + h4);
  float4 gg = *(const float4*)(b + 2048 + h4);
  float4 go = *(const float4*)(b + 3072 + h4);
  for (int s = 0; s < nsplit; s++){
    const float* g = d_gp[s] + base;
    float4 v;
    v = *(const float4*)(g + h4);        gi.x+=v.x; gi.y+=v.y; gi.z+=v.z; gi.w+=v.w;
    v = *(const float4*)(g + 1024 + h4); gf.x+=v.x; gf.y+=v.y; gf.z+=v.z; gf.w+=v.w;
    v = *(const float4*)(g + 2048 + h4); gg.x+=v.x; gg.y+=v.y; gg.z+=v.z; gg.w+=v.w;
    v = *(const float4*)(g + 3072 + h4); go.x+=v.x; go.y+=v.y; go.z+=v.z; go.w+=v.w;
  }
  float4 cv = *(const float4*)(c + (size_t)r*1024 + h4);
  float hn[4];
  {
    float cn;
    cn = sigmoid_(gf.x)*cv.x + sigmoid_(gi.x)*tanh_xla(gg.x); cv.x = cn; hn[0] = sigmoid_(go.x)*tanh_xla(cn);
    cn = sigmoid_(gf.y)*cv.y + sigmoid_(gi.y)*tanh_xla(gg.y); cv.y = cn; hn[1] = sigmoid_(go.y)*tanh_xla(cn);
    cn = sigmoid_(gf.z)*cv.z + sigmoid_(gi.z)*tanh_xla(gg.z); cv.z = cn; hn[2] = sigmoid_(go.z)*tanh_xla(cn);
    cn = sigmoid_(gf.w)*cv.w + sigmoid_(gi.w)*tanh_xla(gg.w); cv.w = cn; hn[3] = sigmoid_(go.w)*tanh_xla(cn);
  }
  *(float4*)(c + (size_t)r*1024 + h4) = cv;
#pragma unroll
  for (int j=0;j<4;j++) hT[(size_t)(h4+j)*64 + r] = hn[j];
}

// ------- logits GEMM (4-stage cp.async) + softmax partials + Gumbel argmax -----
// grid 500 col-tiles of 32; block 128; per-thread 8 rows x 2 cols.
__global__ void __launch_bounds__(128) k_logits(int t,
     const float* __restrict__ W, const float* __restrict__ bout)
{
  __shared__ float As[4][32*64];   // 32 KB
  __shared__ float Ws[4][32*32];   // 16 KB
  const int tid = threadIdx.x, cb = blockIdx.x;
  const int rg = tid >> 4, cg = tid & 15;
  const int cbase = cb * 32;

  unsigned sA[4], sW[4];
#pragma unroll
  for (int i=0;i<4;i++){ sA[i] = su32(&As[i][0]); sW[i] = su32(&Ws[i][0]); }

#define LISSUE(st, K0) {                                                     \
    const float* ap = d_h1T + (size_t)(K0)*64;                               \
    _Pragma("unroll")                                                        \
    for (int i=0;i<4;i++){ int f = i*128 + tid; cpa16(sA[st]+f*16, ap + f*4); } \
    _Pragma("unroll")                                                        \
    for (int i=0;i<2;i++){                                                   \
      int f = i*128 + tid, kk = f >> 3, c4 = (f & 7) * 4;                    \
      cpa16(sW[st]+f*16, W + (size_t)((K0)+kk)*V_ + cbase + c4);             \
    }                                                                        \
    cp_commit(); }

  ull acc[8];
#pragma unroll
  for (int j=0;j<8;j++) acc[j]=0ull;

  LISSUE(0, 0) LISSUE(1, 32) LISSUE(2, 64) LISSUE(3, 96)

  for (int ci=0; ci<32; ci++){
    if      (ci < 29) cp_wait3();
    else if (ci == 29) cp_wait2();
    else if (ci == 30) cp_wait1();
    else               cp_wait0();
    __syncthreads();
    const float* Ac = &As[ci&3][0];
    const float* Wc = &Ws[ci&3][0];
#pragma unroll
    for (int kk=0; kk<32; kk++){
      float4 a0 = *(const float4*)(Ac + kk*64 + rg*8);
      float4 a1 = *(const float4*)(Ac + kk*64 + rg*8 + 4);
      ull w = *(const ull*)(Wc + kk*32 + cg*2);
      fma2(acc[0], pk2(a0.x), w);
      fma2(acc[1], pk2(a0.y), w);
      fma2(acc[2], pk2(a0.z), w);
      fma2(acc[3], pk2(a0.w), w);
      fma2(acc[4], pk2(a1.x), w);
      fma2(acc[5], pk2(a1.y), w);
      fma2(acc[6], pk2(a1.z), w);
      fma2(acc[7], pk2(a1.w), w);
    }
    __syncthreads();
    if (ci+4 < 32){ int st = ci & 3; LISSUE(st, (ci+4)*32) }
  }
#undef LISSUE

  // RNG keys for both passes (stream 0 = free-running rows 0-31, 1 = teacher)
  unsigned k0p[2], k1p[2];
  { unsigned a0,a1; tf2x32(0u,42u,0u,0u,a0,a1); tf2x32(a0,a1,0u,(unsigned)t,k0p[0],k1p[0]); }
  { unsigned a0,a1; tf2x32(0u,42u,0u,1u,a0,a1); tf2x32(a0,a1,0u,(unsigned)t,k0p[1],k1p[1]); }

  float2 bo = *(const float2*)(bout + cbase + cg*2);
  const int c0 = cbase + cg*2, c1 = c0 + 1;
#pragma unroll
  for (int j=0;j<8;j++){
    int row = rg*8 + j;
    int pass = row >> 5, bb = row & 31;
    float2 p = up2(acc[j]);
    float v0 = p.x + bo.x, v1 = p.y + bo.y;
    float m = fmaxf(v0, v1);
#pragma unroll
    for (int msk=8; msk>=1; msk>>=1) m = fmaxf(m, __shfl_xor_sync(0xffffffffu, m, msk));
    float s = __expf(v0-m) + __expf(v1-m);
#pragma unroll
    for (int msk=8; msk>=1; msk>>=1) s += __shfl_xor_sync(0xffffffffu, s, msk);
    float g0 = gumbel_from_bits(pbits(k0p[pass], k1p[pass], (unsigned)(bb*V_ + c0)));
    float g1 = gumbel_from_bits(pbits(k0p[pass], k1p[pass], (unsigned)(bb*V_ + c1)));
    float t0 = v0 + g0, t1 = v1 + g1;
    float bv = t0; int bi = c0;
    if (t1 > bv){ bv = t1; bi = c1; }
#pragma unroll
    for (int msk=8; msk>=1; msk>>=1){
      float ov = __shfl_xor_sync(0xffffffffu, bv, msk);
      int   oi = __shfl_xor_sync(0xffffffffu, bi, msk);
      if (ov > bv || (ov == bv && oi < bi)){ bv = ov; bi = oi; }
    }
    *(float2*)&d_logits[(size_t)row*V_ + c0] = make_float2(v0,v1);
    if (cg == 0){
      d_pmax[row*NBCL_+cb] = m; d_psum[row*NBCL_+cb] = s;
      d_amv [row*NBCL_+cb] = bv; d_ami [row*NBCL_+cb] = bi;
    }
  }
}

// -- per-row: LSE over 500 tiles, global argmax, token update, emb gather -------
__global__ void __launch_bounds__(256) k_argprep(int t, const int* __restrict__ x,
    const float* __restrict__ emb, float* __restrict__ out)
{
  __shared__ float sm[256], ss[256], sv[256];
  __shared__ int   si[256];
  __shared__ int   stok;
  const int row = blockIdx.x, tid = threadIdx.x;
  const float* pm = d_pmax + (size_t)row*NBCL_;
  const float* ps = d_psum + (size_t)row*NBCL_;

  float m = -INFINITY;
  for (int j=tid; j<NBCL_; j+=256) m = fmaxf(m, pm[j]);
  sm[tid] = m; __syncthreads();
  for (int k=128;k>0;k>>=1){ if (tid<k) sm[tid]=fmaxf(sm[tid],sm[tid+k]); __syncthreads(); }
  const float M = sm[0];
  float s = 0.f;
  for (int j=tid; j<NBCL_; j+=256) s += ps[j]*__expf(pm[j]-M);
  ss[tid] = s; __syncthreads();
  for (int k=128;k>0;k>>=1){ if (tid<k) ss[tid]+=ss[tid+k]; __syncthreads(); }
  if (tid == 0){ d_rM[row] = M; d_rL[row] = logf(ss[0]); }

  float bv = -INFINITY; int bi = 0x7fffffff;
  for (int j=tid; j<NBCL_; j+=256){
    float v = d_amv[(size_t)row*NBCL_+j]; int ii = d_ami[(size_t)row*NBCL_+j];
    if (v > bv || (v == bv && ii < bi)){ bv = v; bi = ii; }
  }
  sv[tid] = bv; si[tid] = bi; __syncthreads();
  for (int k=128;k>0;k>>=1){
    if (tid<k){
      float ov = sv[tid+k]; int oi = si[tid+k];
      if (ov > sv[tid] || (ov == sv[tid] && oi < si[tid])){ sv[tid]=ov; si[tid]=oi; }
    }
    __syncthreads();
  }
  if (tid == 0){
    int idx = si[0];
    int pass = row>>5, b = row&31;
    if (pass == 0){ out[(size_t)b*T_ + t] = (float)idx; d_tok[b] = idx; stok = idx; }
    else          { out[(size_t)O_SF + (size_t)b*T_ + t] = (float)idx;
                    stok = x[(size_t)b*T_ + t]; }
  }
  __syncthreads();
  const int tok = stok;
  for (int k = tid; k < E_; k += 256)
    d_A0T[(size_t)k*ROWS_ + row] = emb[(size_t)tok*E_ + k];
}

// ---------------- p = exp(logit - M - L) writer (streaming stores) -------------
// grid 250 tiles of 64 cols; block 256; 4 float4 per thread.
__global__ void __launch_bounds__(256) k_pwrite(int t, float* __restrict__ out)
{
  const int tid = threadIdx.x, cb = blockIdx.x;
  const int cbase = cb * 64;
#pragma unroll
  for (int i=0;i<4;i++){
    int e = i*256 + tid;
    int row = e >> 4, c4 = (e & 15) * 4;
    float ML = d_rM[row] + d_rL[row];
    float4 lg = *(const float4*)&d_logits[(size_t)row*V_ + cbase + c4];
    float4 pv = make_float4(__expf(lg.x-ML), __expf(lg.y-ML),
                            __expf(lg.z-ML), __expf(lg.w-ML));
    int pass = row>>5, b = row&31;
    size_t base = (pass==0) ? (size_t)O_PS + ((size_t)b*T_ + t)*V_
                            : (size_t)O_PF + ((size_t)b*T_ + t)*V_;
    __stcs((float4*)&out[base + cbase + c4], pv);
  }
}

// ---------------- launch -------------------------------------------------------
extern "C" void kernel_launch(void* const* d_in, const int* in_sizes, int n_in,
                              void* d_out, int out_size)
{
  const int*   x    = (const int*)  d_in[0];
  const float* z    = (const float*)d_in[1];
  const float* emb  = (const float*)d_in[2];
  const float* Wx0  = (const float*)d_in[3];
  const float* Wh0  = (const float*)d_in[4];
  const float* b0   = (const float*)d_in[5];
  const float* Wx1  = (const float*)d_in[6];
  const float* Wh1  = (const float*)d_in[7];
  const float* b1   = (const float*)d_in[8];
  const float* Wout = (const float*)d_in[9];
  const float* bout = (const float*)d_in[10];
  float* out = (float*)d_out;

  float* pA0T; cudaGetSymbolAddress((void**)&pA0T, d_A0T);
  float* ph1T; cudaGetSymbolAddress((void**)&ph1T, d_h1T);
  float* pc0;  cudaGetSymbolAddress((void**)&pc0,  d_c0);
  float* pc1;  cudaGetSymbolAddress((void**)&pc1,  d_c1);
  float* pgp;  cudaGetSymbolAddress((void**)&pgp,  d_gp);

  k_init<<<256, 256>>>(z, emb);
  for (int t = 0; t < T_; t++){
    // LSTM0: K=1664 = 13 splits x 128 (grid 64*13)
    k_gemm<<<64*13, 128>>>(pA0T, 1<<30, (const float*)nullptr,
                           Wx0, DIN_, Wh0, pgp);
    k_act <<<32, 512>>>(13, b0, pc0, pA0T + (size_t)DIN_*ROWS_);
    // LSTM1: K=2048 = 16 splits x 128 (grid 64*16)
    k_gemm<<<64*16, 128>>>(pA0T + (size_t)DIN_*ROWS_, H_, ph1T,
                           Wx1, H_, Wh1, pgp);
    k_act <<<32, 512>>>(16, b1, pc1, ph1T);
    k_logits<<<NBCL_, 128>>>(t, Wout, bout);
    k_argprep<<<ROWS_, 256>>>(t, x, emb, out);
    k_pwrite<<<250, 256>>>(t, out);
  }
}

// round 13
// speedup vs baseline: 1.3049x; 1.3049x over previous
#include <cuda_runtime.h>
#include <cuda_fp16.h>
#include <math.h>
#include <stdint.h>

typedef unsigned long long ull;

// Problem constants
#define B_    32
#define T_    128
#define V_    16000
#define E_    512
#define Z_    128
#define H_    1024
#define DIN_  640        // E+Z
#define ROWS_ 64         // 32 sample-pass rows + 32 teacher-forced rows
#define NTIL_ 125        // 16000/128 logits col tiles
#define TINYF 1.17549435e-38f

// Output layout (float32): [s_s (B*T)] [p_s (B*T*V)] [s_f (B*T)] [p_f (B*T*V)]
#define O_PS  4096
#define O_SF  65540096
#define O_PF  65544192

// ---------------- device scratch (static globals; no allocations) -------------
__device__ float d_A0T[(DIN_+H_)*ROWS_];    // [k][64r]; emb rows, z rows, h0^T
__device__ float d_h1T[H_*ROWS_];
__device__ float d_c0[ROWS_*H_];
__device__ float d_c1[ROWS_*H_];
__device__ float d_gp[16][ROWS_*4*H_];      // K-split gate partials
__device__ int   d_tok[B_];
__device__ float d_logits[ROWS_*V_];
__device__ float d_pmax[ROWS_*NTIL_];
__device__ float d_psum[ROWS_*NTIL_];
__device__ float d_amv [ROWS_*NTIL_];
__device__ int   d_ami [ROWS_*NTIL_];
// fp16 planes of Wout in mma.sync B-fragment order: [ng 0..1999][ktg 0..63][lane]
__device__ ull d_wp0[2000*64*32];
__device__ ull d_wp1[2000*64*32];
// fp16 planes of h1, stacked [a0(64 rows); a1(64 rows)] in A-fragment order
__device__ unsigned short d_afrag[8*64*32*8];   // [mt][ktg][lane][8 halfs]

// ---------------- f32x2 packed math helpers ------------------------------------
__device__ __forceinline__ ull pk2(float x){
  ull r; asm("mov.b64 %0,{%1,%1};" : "=l"(r) : "f"(x)); return r;
}
__device__ __forceinline__ void fma2(ull &d, ull a, ull b){
  asm("fma.rn.f32x2 %0, %1, %2, %0;" : "+l"(d) : "l"(a), "l"(b));
}
__device__ __forceinline__ float2 up2(ull v){
  float2 f; asm("mov.b64 {%0,%1},%2;" : "=f"(f.x), "=f"(f.y) : "l"(v)); return f;
}

// ---------------- cp.async helpers ---------------------------------------------
__device__ __forceinline__ unsigned su32(const void* p){
  return (unsigned)__cvta_generic_to_shared(p);
}
__device__ __forceinline__ void cpa16(unsigned s, const void* g){
  asm volatile("cp.async.ca.shared.global [%0], [%1], 16;" :: "r"(s), "l"(g));
}
__device__ __forceinline__ void cp_commit(){ asm volatile("cp.async.commit_group;"); }
__device__ __forceinline__ void cp_wait1(){ asm volatile("cp.async.wait_group 1;"); }
__device__ __forceinline__ void cp_wait0(){ asm volatile("cp.async.wait_group 0;"); }

// ---------------- mma.sync m16n8k16 fp16 ----------------------------------------
__device__ __forceinline__ void mma16816(float* d, const unsigned* a, const unsigned* b){
  asm volatile("mma.sync.aligned.m16n8k16.row.col.f32.f16.f16.f32 "
    "{%0,%1,%2,%3}, {%4,%5,%6,%7}, {%8,%9}, {%0,%1,%2,%3};"
    : "+f"(d[0]), "+f"(d[1]), "+f"(d[2]), "+f"(d[3])
    : "r"(a[0]), "r"(a[1]), "r"(a[2]), "r"(a[3]), "r"(b[0]), "r"(b[1]));
}

// ---------------- XLA-exact tanh (Eigen-style rational) ------------------------
__device__ __forceinline__ float tanh_xla(float x){
  float ax = fabsf(x);
  if (ax < 0.0004f) return x;
  float xc = fminf(fmaxf(x, -7.90531110763549805f), 7.90531110763549805f);
  float x2 = xc*xc;
  float p = fmaf(x2, -2.76076847742355e-16f, 2.00018790482477e-13f);
  p = fmaf(x2, p, -8.60467152213735e-11f);
  p = fmaf(x2, p,  5.12229709037114e-08f);
  p = fmaf(x2, p,  1.48572235717979e-05f);
  p = fmaf(x2, p,  6.37261928875436e-04f);
  p = fmaf(x2, p,  4.89352455891786e-03f);
  p = xc * p;
  float q = fmaf(x2, 1.19825839466702e-06f, 1.18534705686654e-04f);
  q = fmaf(x2, q, 2.26843463243900e-03f);
  q = fmaf(x2, q, 4.89352518554385e-03f);
  return p / q;
}
__device__ __forceinline__ float sigmoid_(float x){ return 0.5f + 0.5f*tanh_xla(0.5f*x); }

// ---------------- threefry2x32 (JAX partitionable) ----------------------------
__device__ __forceinline__ void tf2x32(unsigned k0, unsigned k1, unsigned x0, unsigned x1,
                                       unsigned &o0, unsigned &o1){
  unsigned k2 = k0 ^ k1 ^ 0x1BD11BDAu;
  x0 += k0; x1 += k1;
#define TFR(r) { x0 += x1; x1 = (x1<<(r)) | (x1>>(32-(r))); x1 ^= x0; }
  TFR(13) TFR(15) TFR(26) TFR(6)
  x0 += k1; x1 += k2 + 1u;
  TFR(17) TFR(29) TFR(16) TFR(24)
  x0 += k2; x1 += k0 + 2u;
  TFR(13) TFR(15) TFR(26) TFR(6)
  x0 += k0; x1 += k1 + 3u;
  TFR(17) TFR(29) TFR(16) TFR(24)
  x0 += k1; x1 += k2 + 4u;
  TFR(13) TFR(15) TFR(26) TFR(6)
  x0 += k2; x1 += k0 + 5u;
#undef TFR
  o0 = x0; o1 = x1;
}
__device__ __forceinline__ unsigned pbits(unsigned k0, unsigned k1, unsigned j){
  unsigned o0, o1; tf2x32(k0, k1, 0u, j, o0, o1); return o0 ^ o1;
}
__device__ __forceinline__ float gumbel_from_bits(unsigned bits){
  float f = __uint_as_float((bits>>9) | 0x3f800000u) - 1.0f;
  float u = fmaxf(TINYF, f + TINYF);
  return -logf(-logf(u));
}

// ---------------- init ---------------------------------------------------------
__global__ void k_init(const float* __restrict__ z, const float* __restrict__ emb){
  int i = blockIdx.x*blockDim.x + threadIdx.x;
  if (i < ROWS_*H_){
    d_A0T[DIN_*ROWS_ + i] = 0.f;    // h0^T = 0
    d_h1T[i] = 0.f;
    d_c0[i] = 0.f; d_c1[i] = 0.f;
  }
  if (i < Z_*ROWS_){
    int zz = i >> 6, r = i & 63;
    d_A0T[(E_+zz)*ROWS_ + r] = z[(r&31)*Z_ + zz];
  }
  if (i < E_*ROWS_){
    int k = i >> 6, r = i & 63;
    d_A0T[(size_t)k*ROWS_ + r] = emb[(size_t)E_ + k];
  }
  if (i < B_) d_tok[i] = 1;
}

// ---- pre-pack Wout into 2 fp16 planes, mma.sync B-fragment order --------------
// thread = (frag = ng*64+ktg, lane). B frag (16k x 8n): lane l holds
// reg0 = W[k0, n],W[k0+1, n]; reg1 = W[k0+8, n],W[k0+9, n]; k0=ktg*16+(l%4)*2, n=ng*8+l/4.
__global__ void k_bpack(const float* __restrict__ W){
  unsigned idx = blockIdx.x*256 + threadIdx.x;   // 4,096,000 exactly
  unsigned lane = idx & 31, frag = idx >> 5;
  unsigned ktg = frag & 63, ng = frag >> 6;
  int k0 = ktg*16 + (lane&3)*2;
  int n  = ng*8 + (lane>>2);
  float w00 = W[(size_t)k0*V_ + n];
  float w01 = W[(size_t)(k0+1)*V_ + n];
  float w10 = W[(size_t)(k0+8)*V_ + n];
  float w11 = W[(size_t)(k0+9)*V_ + n];
  __half h00=__float2half_rn(w00), h01=__float2half_rn(w01);
  __half h10=__float2half_rn(w10), h11=__float2half_rn(w11);
  __half r00=__float2half_rn(w00-__half2float(h00));
  __half r01=__float2half_rn(w01-__half2float(h01));
  __half r10=__float2half_rn(w10-__half2float(h10));
  __half r11=__float2half_rn(w11-__half2float(h11));
  unsigned p0a = (unsigned)__half_as_ushort(h00) | ((unsigned)__half_as_ushort(h01)<<16);
  unsigned p0b = (unsigned)__half_as_ushort(h10) | ((unsigned)__half_as_ushort(h11)<<16);
  unsigned p1a = (unsigned)__half_as_ushort(r00) | ((unsigned)__half_as_ushort(r01)<<16);
  unsigned p1b = (unsigned)__half_as_ushort(r10) | ((unsigned)__half_as_ushort(r11)<<16);
  d_wp0[(size_t)frag*32 + lane] = (ull)p0a | ((ull)p0b << 32);
  d_wp1[(size_t)frag*32 + lane] = (ull)p1a | ((ull)p1b << 32);
}

// ---- K-split GEMM (round-7 exact): [64 x K]^T A @ [K x 4096] W, f32x2 ---------
__global__ void __launch_bounds__(128) k_gemm(
    const float* __restrict__ A1, int alen1, const float* __restrict__ A2,
    const float* __restrict__ W1, int wlen1, const float* __restrict__ W2,
    float* __restrict__ gp)
{
  __shared__ float As[2][32*64];
  __shared__ float Ws[2][32*64];
  const int tid = threadIdx.x;
  const int ct = blockIdx.x & 63, sp = blockIdx.x >> 6;
  const int rg = tid >> 4, cg = tid & 15;
  const int kbeg = sp * 128;
  const int cbase = ct * 64;

  const unsigned sA0 = su32(&As[0][0]), sA1 = su32(&As[1][0]);
  const unsigned sW0 = su32(&Ws[0][0]), sW1 = su32(&Ws[1][0]);

#define ISSUE(sa, sw, K0) {                                                  \
    const float* ap = ((K0) < alen1) ? (A1 + (size_t)(K0)*64)                \
                                     : (A2 + (size_t)((K0)-alen1)*64);       \
    const float* wp = ((K0) < wlen1) ? (W1 + (size_t)(K0)*4096)              \
                                     : (W2 + (size_t)((K0)-wlen1)*4096);     \
    _Pragma("unroll")                                                        \
    for (int i=0;i<4;i++){                                                   \
      int f = i*128 + tid;                                                   \
      cpa16((sa) + f*16, ap + f*4);                                          \
      int kk = f >> 4, c4 = (f & 15) * 4;                                    \
      cpa16((sw) + f*16, wp + (size_t)kk*4096 + cbase + c4);                 \
    }                                                                        \
    cp_commit(); }

  ull acc[8][2];
#pragma unroll
  for (int j=0;j<8;j++){ acc[j][0]=0ull; acc[j][1]=0ull; }

  ISSUE(sA0, sW0, kbeg)
  ISSUE(sA1, sW1, kbeg+32)

#pragma unroll
  for (int ci = 0; ci < 4; ci++){
    if (ci < 3) cp_wait1(); else cp_wait0();
    __syncthreads();
    const float* Ac = &As[ci&1][0];
    const float* Wc = &Ws[ci&1][0];
#pragma unroll
    for (int kk=0; kk<32; kk++){
      float4 a0 = *(const float4*)(Ac + kk*64 + rg*8);
      float4 a1 = *(const float4*)(Ac + kk*64 + rg*8 + 4);
      ulonglong2 w = *(const ulonglong2*)(Wc + kk*64 + cg*4);
      ull pa;
      pa = pk2(a0.x); fma2(acc[0][0],pa,w.x); fma2(acc[0][1],pa,w.y);
      pa = pk2(a0.y); fma2(acc[1][0],pa,w.x); fma2(acc[1][1],pa,w.y);
      pa = pk2(a0.z); fma2(acc[2][0],pa,w.x); fma2(acc[2][1],pa,w.y);
      pa = pk2(a0.w); fma2(acc[3][0],pa,w.x); fma2(acc[3][1],pa,w.y);
      pa = pk2(a1.x); fma2(acc[4][0],pa,w.x); fma2(acc[4][1],pa,w.y);
      pa = pk2(a1.y); fma2(acc[5][0],pa,w.x); fma2(acc[5][1],pa,w.y);
      pa = pk2(a1.z); fma2(acc[6][0],pa,w.x); fma2(acc[6][1],pa,w.y);
      pa = pk2(a1.w); fma2(acc[7][0],pa,w.x); fma2(acc[7][1],pa,w.y);
    }
    __syncthreads();
    if (ci+2 < 4){
      if ((ci&1)==0){ ISSUE(sA0, sW0, kbeg+(ci+2)*32) }
      else          { ISSUE(sA1, sW1, kbeg+(ci+2)*32) }
    }
  }

  float* op = gp + (size_t)sp*ROWS_*4096;
#pragma unroll
  for (int j=0;j<8;j++){
    int r = rg*8 + j;
    float2 p0 = up2(acc[j][0]), p1 = up2(acc[j][1]);
    *(float4*)(op + (size_t)r*4096 + cbase + cg*4) = make_float4(p0.x,p0.y,p1.x,p1.y);
  }
#undef ISSUE
}

// ---------------- bias + LSTM activation; writes h^T (+ optional A-frags) ------
__global__ void __launch_bounds__(512) k_act(int nsplit, const float* __restrict__ b,
    float* __restrict__ c, float* __restrict__ hT, unsigned short* afrag)
{
  int idx = blockIdx.x*512 + threadIdx.x;      // 65536
  int h = idx & 1023, r = idx >> 10;
  size_t base = (size_t)r*4096;
  float gi = b[h], gf = b[1024+h], gg = b[2048+h], go = b[3072+h];
  for (int s = 0; s < nsplit; s++){
    const float* g = d_gp[s] + base;
    gi += g[h]; gf += g[1024+h]; gg += g[2048+h]; go += g[3072+h];
  }
  float cv = c[(size_t)r*1024 + h];
  float cn = sigmoid_(gf)*cv + sigmoid_(gi)*tanh_xla(gg);
  c[(size_t)r*1024 + h] = cn;
  float hn = sigmoid_(go)*tanh_xla(cn);
  hT[(size_t)h*64 + r]  = hn;
  if (afrag){
    __half h16 = __float2half_rn(hn);
    __half r16 = __float2half_rn(hn - __half2float(h16));
    int kt = h >> 4, ci = h & 15;
#pragma unroll
    for (int p = 0; p < 2; p++){
      int R = r + 64*p;
      int mt = R >> 4, ri = R & 15;
      int lane = (ri & 7)*4 + ((ci & 7) >> 1);
      int reg  = (ri >> 3) + ((ci >> 3) << 1);
      size_t off = (((size_t)(mt*64 + kt))*32 + lane)*8 + reg*2 + (ci & 1);
      afrag[off] = __half_as_ushort(p ? r16 : h16);
    }
  }
}

// ------- mma.sync fp16x2 logits GEMM + softmax partials + Gumbel argmax --------
// grid 125 CTAs (one 128-col tile), 256 threads (8 warps, 2 n-tiles each).
// D = [a0;a1](128) x b0  plus  a0(64) x b1 ;  out = D[a0]+D[a1]+D2.
__global__ void __launch_bounds__(256, 1) k_logits_mma(int t,
     const float* __restrict__ bout)
{
  extern __shared__ char smem[];
  const unsigned smb = su32(smem);
  const int tid = threadIdx.x, wid = tid >> 5, lane = tid & 31;
  const int cb = blockIdx.x;
  const int ng0 = cb*16 + wid*2;

  float* LG = (float*)(smem + 32768);    // [64][136]

#define FILL_A(s, ck) {                                                      \
    unsigned dst = smb + (s)*16384;                                          \
    const char* src = (const char*)d_afrag;                                  \
    _Pragma("unroll")                                                        \
    for (int i=0;i<4;i++){                                                   \
      int u = i*256 + tid;                                                   \
      int f = u >> 5, lh = u & 31;                                           \
      int mt = f >> 2, ktl = f & 3;                                          \
      size_t so = (((size_t)(mt*64 + (ck)*4 + ktl))*32 + lh)*16;             \
      cpa16(dst + u*16, src + so);                                           \
    }                                                                        \
    cp_commit(); }

  float D1[8][2][4], D2[4][2][4];
#pragma unroll
  for (int mt=0;mt<8;mt++)
#pragma unroll
    for (int nt=0;nt<2;nt++){ D1[mt][nt][0]=0.f;D1[mt][nt][1]=0.f;D1[mt][nt][2]=0.f;D1[mt][nt][3]=0.f; }
#pragma unroll
  for (int mt=0;mt<4;mt++)
#pragma unroll
    for (int nt=0;nt<2;nt++){ D2[mt][nt][0]=0.f;D2[mt][nt][1]=0.f;D2[mt][nt][2]=0.f;D2[mt][nt][3]=0.f; }

  FILL_A(0, 0)
  FILL_A(1, 1)

  for (int c = 0; c < 16; c++){
    if (c < 15) cp_wait1(); else cp_wait0();
    __syncthreads();
    const unsigned short* smA = (const unsigned short*)(smem + (c&1)*16384);
#pragma unroll
    for (int ktl = 0; ktl < 4; ktl++){
      int ktg = c*4 + ktl;
      unsigned b0[2][2], b1[2][2];
#pragma unroll
      for (int nt=0; nt<2; nt++){
        size_t bi = ((size_t)((ng0+nt)*64 + ktg))*32 + lane;
        ull v0 = d_wp0[bi], v1 = d_wp1[bi];
        b0[nt][0]=(unsigned)v0; b0[nt][1]=(unsigned)(v0>>32);
        b1[nt][0]=(unsigned)v1; b1[nt][1]=(unsigned)(v1>>32);
      }
#pragma unroll
      for (int mt=0; mt<4; mt++){
        uint4 av = *(const uint4*)(smA + (size_t)(mt*4+ktl)*256 + lane*8);
        unsigned a[4] = {av.x, av.y, av.z, av.w};
#pragma unroll
        for (int nt=0;nt<2;nt++){
          mma16816(D1[mt][nt], a, b0[nt]);
          mma16816(D2[mt][nt], a, b1[nt]);
        }
      }
#pragma unroll
      for (int mt=4; mt<8; mt++){
        uint4 av = *(const uint4*)(smA + (size_t)(mt*4+ktl)*256 + lane*8);
        unsigned a[4] = {av.x, av.y, av.z, av.w};
#pragma unroll
        for (int nt=0;nt<2;nt++) mma16816(D1[mt][nt], a, b0[nt]);
      }
    }
    __syncthreads();
    if (c+2 < 16){ FILL_A((c&1), c+2) }
  }
#undef FILL_A

  // combine into LG[64][136]: out = D1[a0 rows] + D1[a1 rows] + D2
#pragma unroll
  for (int mt=0; mt<4; mt++)
#pragma unroll
    for (int nt=0; nt<2; nt++)
#pragma unroll
      for (int e=0; e<4; e++){
        int row = mt*16 + (lane>>2) + ((e>>1)<<3);
        int col = wid*16 + nt*8 + (lane&3)*2 + (e&1);
        LG[row*136 + col] = D1[mt][nt][e] + D1[mt+4][nt][e] + D2[mt][nt][e];
      }
  __syncthreads();

  // bias + per-tile softmax partials + Gumbel argmax (row = tid/4, 32 cols each)
  unsigned k0p[2], k1p[2];
  { unsigned a0,a1; tf2x32(0u,42u,0u,0u,a0,a1); tf2x32(a0,a1,0u,(unsigned)t,k0p[0],k1p[0]); }
  { unsigned a0,a1; tf2x32(0u,42u,0u,1u,a0,a1); tf2x32(a0,a1,0u,(unsigned)t,k0p[1],k1p[1]); }

  const int row = tid >> 2, q = tid & 3;
  const int pass = row >> 5, bb = row & 31;
  float m = -INFINITY;
#pragma unroll 4
  for (int j=0;j<32;j++){
    int cl = q*32 + j;
    float v = LG[row*136 + cl] + bout[cb*128 + cl];
    LG[row*136 + cl] = v;
    m = fmaxf(m, v);
  }
  m = fmaxf(m, __shfl_xor_sync(0xffffffffu, m, 1));
  m = fmaxf(m, __shfl_xor_sync(0xffffffffu, m, 2));
  float s = 0.f, bv = -INFINITY; int bi = 0x7fffffff;
  for (int j=0;j<32;j++){
    int cl = q*32 + j, cgl = cb*128 + cl;
    float v = LG[row*136 + cl];
    s += __expf(v - m);
    float g = gumbel_from_bits(pbits(k0p[pass], k1p[pass], (unsigned)(bb*V_ + cgl)));
    float tv = v + g;
    if (tv > bv){ bv = tv; bi = cgl; }
  }
  s += __shfl_xor_sync(0xffffffffu, s, 1);
  s += __shfl_xor_sync(0xffffffffu, s, 2);
#pragma unroll
  for (int msk=1; msk<=2; msk<<=1){
    float ov = __shfl_xor_sync(0xffffffffu, bv, msk);
    int   oi = __shfl_xor_sync(0xffffffffu, bi, msk);
    if (ov > bv || (ov == bv && oi < bi)){ bv = ov; bi = oi; }
  }
  if (q == 0){
    d_pmax[row*NTIL_+cb] = m; d_psum[row*NTIL_+cb] = s;
    d_amv [row*NTIL_+cb] = bv; d_ami [row*NTIL_+cb] = bi;
  }
  __syncthreads();

  // coalesced logits store
#pragma unroll
  for (int i=0;i<8;i++){
    int e2 = i*256 + tid;
    int rr = e2 >> 5, c4 = (e2 & 31) * 4;
    float4 v = *(const float4*)&LG[rr*136 + c4];
    *(float4*)&d_logits[(size_t)rr*V_ + cb*128 + c4] = v;
  }
}

// ------- fused: row LSE (recomputed per block) + p write + argmax/token --------
// grid 250 tiles of 64 cols; block 256. Blocks 0..63 also do row argmax + token.
__global__ void __launch_bounds__(256) k_final(int t, const int* __restrict__ x,
    const float* __restrict__ emb, float* __restrict__ out)
{
  __shared__ float tmpM[4][ROWS_], tmpS[4][ROWS_];
  __shared__ float sM[ROWS_], sL[ROWS_];
  __shared__ float sv[256];
  __shared__ int   si[256];
  __shared__ int   stok;
  const int tid = threadIdx.x, cb = blockIdx.x;

  // Phase A: per-row log-sum-exp over 125 tile partials (4 threads per row)
  {
    const int row = tid >> 2, part = tid & 3;
    const float* pm = d_pmax + (size_t)row*NTIL_;
    const float* ps = d_psum + (size_t)row*NTIL_;
    float m = -INFINITY;
    for (int j = part; j < NTIL_; j += 4) m = fmaxf(m, pm[j]);
    tmpM[part][row] = m;
    __syncthreads();
    float M = fmaxf(fmaxf(tmpM[0][row], tmpM[1][row]), fmaxf(tmpM[2][row], tmpM[3][row]));
    float s = 0.f;
    for (int j = part; j < NTIL_; j += 4) s += ps[j]*__expf(pm[j]-M);
    tmpS[part][row] = s;
    __syncthreads();
    if (part == 0){
      sM[row] = M;
      sL[row] = logf((tmpS[0][row]+tmpS[1][row]) + (tmpS[2][row]+tmpS[3][row]));
    }
    __syncthreads();
  }

  // Phase B: p = exp(logit - M - L) for this 64-col tile
  const int cbase = cb * 64;
#pragma unroll
  for (int i=0;i<4;i++){
    int e = i*256 + tid;
    int row = e >> 4, c4 = (e & 15) * 4;
    float ML = sM[row] + sL[row];
    float4 lg = *(const float4*)&d_logits[(size_t)row*V_ + cbase + c4];
    float4 pv = make_float4(__expf(lg.x-ML), __expf(lg.y-ML),
                            __expf(lg.z-ML), __expf(lg.w-ML));
    int pass = row>>5, b = row&31;
    size_t base = (pass==0) ? (size_t)O_PS + ((size_t)b*T_ + t)*V_
                            : (size_t)O_PF + ((size_t)b*T_ + t)*V_;
    *(float4*)&out[base + cbase + c4] = pv;
  }

  // Phase C (blocks 0..63): global argmax for row=cb, token update, emb gather
  if (cb < ROWS_){
    const int row = cb;
    float bv = -INFINITY; int bi = 0x7fffffff;
    for (int j=tid; j<NTIL_; j+=256){
      float v = d_amv[(size_t)row*NTIL_+j]; int ii = d_ami[(size_t)row*NTIL_+j];
      if (v > bv || (v == bv && ii < bi)){ bv = v; bi = ii; }
    }
    sv[tid] = bv; si[tid] = bi; __syncthreads();
    for (int k=128;k>0;k>>=1){
      if (tid<k){
        float ov = sv[tid+k]; int oi = si[tid+k];
        if (ov > sv[tid] || (ov == sv[tid] && oi < si[tid])){ sv[tid]=ov; si[tid]=oi; }
      }
      __syncthreads();
    }
    if (tid == 0){
      int idx = si[0];
      int pass = row>>5, b = row&31;
      if (pass == 0){ out[(size_t)b*T_ + t] = (float)idx; d_tok[b] = idx; stok = idx; }
      else          { out[(size_t)O_SF + (size_t)b*T_ + t] = (float)idx;
                      stok = x[(size_t)b*T_ + t]; }
    }
    __syncthreads();
    const int tok = stok;
    for (int k = tid; k < E_; k += 256)
      d_A0T[(size_t)k*ROWS_ + row] = emb[(size_t)tok*E_ + k];
  }
}

// ---------------- launch -------------------------------------------------------
extern "C" void kernel_launch(void* const* d_in, const int* in_sizes, int n_in,
                              void* d_out, int out_size)
{
  const int*   x    = (const int*)  d_in[0];
  const float* z    = (const float*)d_in[1];
  const float* emb  = (const float*)d_in[2];
  const float* Wx0  = (const float*)d_in[3];
  const float* Wh0  = (const float*)d_in[4];
  const float* b0   = (const float*)d_in[5];
  const float* Wx1  = (const float*)d_in[6];
  const float* Wh1  = (const float*)d_in[7];
  const float* b1   = (const float*)d_in[8];
  const float* Wout = (const float*)d_in[9];
  const float* bout = (const float*)d_in[10];
  float* out = (float*)d_out;

  float* pA0T; cudaGetSymbolAddress((void**)&pA0T, d_A0T);
  float* ph1T; cudaGetSymbolAddress((void**)&ph1T, d_h1T);
  float* pc0;  cudaGetSymbolAddress((void**)&pc0,  d_c0);
  float* pc1;  cudaGetSymbolAddress((void**)&pc1,  d_c1);
  float* pgp;  cudaGetSymbolAddress((void**)&pgp,  d_gp);
  unsigned short* paf; cudaGetSymbolAddress((void**)&paf, d_afrag);

  const int SMEM_LG = 32768 + 64*136*4;   // A stages + LG = 67584 bytes
  static int attr_set = 0;
  if (!attr_set){
    cudaFuncSetAttribute(k_logits_mma, cudaFuncAttributeMaxDynamicSharedMemorySize, SMEM_LG);
    attr_set = 1;
  }

  k_init<<<256, 256>>>(z, emb);
  k_bpack<<<16000, 256>>>(Wout);
  for (int t = 0; t < T_; t++){
    k_gemm<<<64*13, 128>>>(pA0T, 1<<30, (const float*)nullptr,
                           Wx0, DIN_, Wh0, pgp);
    k_act <<<128, 512>>>(13, b0, pc0, pA0T + (size_t)DIN_*ROWS_, (unsigned short*)nullptr);
    k_gemm<<<64*16, 128>>>(pA0T + (size_t)DIN_*ROWS_, H_, ph1T,
                           Wx1, H_, Wh1, pgp);
    k_act <<<128, 512>>>(16, b1, pc1, ph1T, paf);
    k_logits_mma<<<NTIL_, 256, SMEM_LG>>>(t, bout);
    k_final<<<250, 256>>>(t, x, emb, out);
  }
}

// round 15
// speedup vs baseline: 1.4665x; 1.1239x over previous
#include <cuda_runtime.h>
#include <cuda_fp16.h>
#include <math.h>
#include <stdint.h>

typedef unsigned long long ull;

// Problem constants
#define B_    32
#define T_    128
#define V_    16000
#define E_    512
#define Z_    128
#define H_    1024
#define ROWS_ 64         // 32 sample-pass rows + 32 teacher-forced rows
#define NTIL_ 125        // 16000/128 logits col tiles
#define NKT0_ 104        // lstm0 K=1664 /16
#define NKT1_ 128        // lstm1 K=2048 /16
#define TINYF 1.17549435e-38f

// Output layout (float32): [s_s (B*T)] [p_s (B*T*V)] [s_f (B*T)] [p_f (B*T*V)]
#define O_PS  4096
#define O_SF  65540096
#define O_PF  65544192

// ---------------- device scratch (static globals; no allocations) -------------
__device__ float d_c0[ROWS_*H_];
__device__ float d_c1[ROWS_*H_];
__device__ float d_gp[4][ROWS_*4*H_];       // K-split gate partials
__device__ int   d_tok[B_];
__device__ float d_logits[ROWS_*V_];
__device__ float d_pmax[ROWS_*NTIL_];
__device__ float d_psum[ROWS_*NTIL_];
__device__ float d_amv [ROWS_*NTIL_];
__device__ int   d_ami [ROWS_*NTIL_];
// fp16 planes of Wout in mma.sync B-fragment order: [ng 0..1999][ktg 0..63][lane]
__device__ ull d_wp0[2000*64*32];
__device__ ull d_wp1[2000*64*32];
// fp16 planes of LSTM weights in B-fragment order: [ng 0..511][ktg][lane]
__device__ ull d_wb0a[512*NKT0_*32];
__device__ ull d_wb0b[512*NKT0_*32];
__device__ ull d_wb1a[512*NKT1_*32];
__device__ ull d_wb1b[512*NKT1_*32];
// A-fragment buffers, stacked [a0(64 rows); a1(64 rows)]: [mt 0..7][ktg][lane][8]
__device__ unsigned short d_af0[8*NKT0_*32*8];   // lstm0: emb | z | h0
__device__ unsigned short d_af1[8*NKT1_*32*8];   // lstm1: h0 | h1   (h1 = logits A)

// ---------------- cp.async helpers ---------------------------------------------
__device__ __forceinline__ unsigned su32(const void* p){
  return (unsigned)__cvta_generic_to_shared(p);
}
__device__ __forceinline__ void cpa16(unsigned s, const void* g){
  asm volatile("cp.async.ca.shared.global [%0], [%1], 16;" :: "r"(s), "l"(g));
}
__device__ __forceinline__ void cp_commit(){ asm volatile("cp.async.commit_group;"); }
__device__ __forceinline__ void cp_wait1(){ asm volatile("cp.async.wait_group 1;"); }
__device__ __forceinline__ void cp_wait0(){ asm volatile("cp.async.wait_group 0;"); }

// ---------------- mma.sync m16n8k16 fp16 ----------------------------------------
__device__ __forceinline__ void mma16816(float* d, const unsigned* a, const unsigned* b){
  asm volatile("mma.sync.aligned.m16n8k16.row.col.f32.f16.f16.f32 "
    "{%0,%1,%2,%3}, {%4,%5,%6,%7}, {%8,%9}, {%0,%1,%2,%3};"
    : "+f"(d[0]), "+f"(d[1]), "+f"(d[2]), "+f"(d[3])
    : "r"(a[0]), "r"(a[1]), "r"(a[2]), "r"(a[3]), "r"(b[0]), "r"(b[1]));
}

// ---- scatter one value's 2 fp16 planes into stacked A-fragment layout ----------
__device__ __forceinline__ void wfrag(unsigned short* buf, int nk, int r, int kidx, float v){
  __half h16 = __float2half_rn(v);
  __half r16 = __float2half_rn(v - __half2float(h16));
  int kt = kidx >> 4, ci = kidx & 15;
#pragma unroll
  for (int p = 0; p < 2; p++){
    int R = r + 64*p;
    int mt = R >> 4, ri = R & 15;
    int lane = (ri & 7)*4 + ((ci & 7) >> 1);
    int reg  = (ri >> 3) + ((ci >> 3) << 1);
    size_t off = (((size_t)(mt*nk + kt))*32 + lane)*8 + reg*2 + (ci & 1);
    buf[off] = __half_as_ushort(p ? r16 : h16);
  }
}

// ---------------- XLA-exact tanh (Eigen-style rational) ------------------------
__device__ __forceinline__ float tanh_xla(float x){
  float ax = fabsf(x);
  if (ax < 0.0004f) return x;
  float xc = fminf(fmaxf(x, -7.90531110763549805f), 7.90531110763549805f);
  float x2 = xc*xc;
  float p = fmaf(x2, -2.76076847742355e-16f, 2.00018790482477e-13f);
  p = fmaf(x2, p, -8.60467152213735e-11f);
  p = fmaf(x2, p,  5.12229709037114e-08f);
  p = fmaf(x2, p,  1.48572235717979e-05f);
  p = fmaf(x2, p,  6.37261928875436e-04f);
  p = fmaf(x2, p,  4.89352455891786e-03f);
  p = xc * p;
  float q = fmaf(x2, 1.19825839466702e-06f, 1.18534705686654e-04f);
  q = fmaf(x2, q, 2.26843463243900e-03f);
  q = fmaf(x2, q, 4.89352518554385e-03f);
  return p / q;
}
__device__ __forceinline__ float sigmoid_(float x){ return 0.5f + 0.5f*tanh_xla(0.5f*x); }

// ---------------- threefry2x32 (JAX partitionable) ----------------------------
__device__ __forceinline__ void tf2x32(unsigned k0, unsigned k1, unsigned x0, unsigned x1,
                                       unsigned &o0, unsigned &o1){
  unsigned k2 = k0 ^ k1 ^ 0x1BD11BDAu;
  x0 += k0; x1 += k1;
#define TFR(r) { x0 += x1; x1 = (x1<<(r)) | (x1>>(32-(r))); x1 ^= x0; }
  TFR(13) TFR(15) TFR(26) TFR(6)
  x0 += k1; x1 += k2 + 1u;
  TFR(17) TFR(29) TFR(16) TFR(24)
  x0 += k2; x1 += k0 + 2u;
  TFR(13) TFR(15) TFR(26) TFR(6)
  x0 += k0; x1 += k1 + 3u;
  TFR(17) TFR(29) TFR(16) TFR(24)
  x0 += k1; x1 += k2 + 4u;
  TFR(13) TFR(15) TFR(26) TFR(6)
  x0 += k2; x1 += k0 + 5u;
#undef TFR
  o0 = x0; o1 = x1;
}
__device__ __forceinline__ unsigned pbits(unsigned k0, unsigned k1, unsigned j){
  unsigned o0, o1; tf2x32(k0, k1, 0u, j, o0, o1); return o0 ^ o1;
}
__device__ __forceinline__ float gumbel_from_bits(unsigned bits){
  float f = __uint_as_float((bits>>9) | 0x3f800000u) - 1.0f;
  float u = fmaxf(TINYF, f + TINYF);
  return -logf(-logf(u));
}

// ---------------- init: zero states + A-frag buffers ---------------------------
__global__ void k_init(){
  int i = blockIdx.x*blockDim.x + threadIdx.x;   // 65536
  d_c0[i] = 0.f; d_c1[i] = 0.f;
  ull* a0 = (ull*)d_af0;    // 212,992 ull
  ull* a1 = (ull*)d_af1;    // 262,144 ull
  for (int j = i; j < 8*NKT0_*32; j += 65536) a0[j] = 0ull;
  for (int j = i; j < 8*NKT1_*32; j += 65536) a1[j] = 0ull;
  if (i < B_) d_tok[i] = 1;
}

// ---------------- fill z rows + START-token emb rows of lstm0 A ----------------
__global__ void k_fillA(const float* __restrict__ z, const float* __restrict__ emb){
  int idx = blockIdx.x*256 + threadIdx.x;   // 40960
  if (idx < 8192){                          // z: k = 512 + zz
    int r = idx & 63, zz = idx >> 6;
    wfrag(d_af0, NKT0_, r, 512 + zz, z[(r&31)*Z_ + zz]);
  } else {                                  // emb START (token 1): k = 0..511
    int e = idx - 8192;
    int r = e & 63, k = e >> 6;
    wfrag(d_af0, NKT0_, r, k, emb[(size_t)E_ + k]);
  }
}

// ---- pre-pack LSTM weights into 2 fp16 planes, B-fragment order ---------------
__global__ void k_wpack(const float* __restrict__ W1, int wlen1,
                        const float* __restrict__ W2, int nktg,
                        ull* __restrict__ pa, ull* __restrict__ pb){
  size_t idx = (size_t)blockIdx.x*256 + threadIdx.x;
  if (idx >= (size_t)512*nktg*32) return;
  unsigned lane = idx & 31, frag = (unsigned)(idx >> 5);
  unsigned ktg = frag % nktg, ng = frag / nktg;
  int k0 = ktg*16 + (lane&3)*2;
  int n  = ng*8 + (lane>>2);
  const float* r0 = (k0   < wlen1) ? W1 + (size_t)k0*4096     : W2 + (size_t)(k0-wlen1)*4096;
  const float* r1 = (k0+1 < wlen1) ? W1 + (size_t)(k0+1)*4096 : W2 + (size_t)(k0+1-wlen1)*4096;
  const float* r8 = (k0+8 < wlen1) ? W1 + (size_t)(k0+8)*4096 : W2 + (size_t)(k0+8-wlen1)*4096;
  const float* r9 = (k0+9 < wlen1) ? W1 + (size_t)(k0+9)*4096 : W2 + (size_t)(k0+9-wlen1)*4096;
  float w00 = r0[n], w01 = r1[n], w10 = r8[n], w11 = r9[n];
  __half h00=__float2half_rn(w00), h01=__float2half_rn(w01);
  __half h10=__float2half_rn(w10), h11=__float2half_rn(w11);
  __half q00=__float2half_rn(w00-__half2float(h00));
  __half q01=__float2half_rn(w01-__half2float(h01));
  __half q10=__float2half_rn(w10-__half2float(h10));
  __half q11=__float2half_rn(w11-__half2float(h11));
  unsigned p0a = (unsigned)__half_as_ushort(h00) | ((unsigned)__half_as_ushort(h01)<<16);
  unsigned p0b = (unsigned)__half_as_ushort(h10) | ((unsigned)__half_as_ushort(h11)<<16);
  unsigned p1a = (unsigned)__half_as_ushort(q00) | ((unsigned)__half_as_ushort(q01)<<16);
  unsigned p1b = (unsigned)__half_as_ushort(q10) | ((unsigned)__half_as_ushort(q11)<<16);
  pa[idx] = (ull)p0a | ((ull)p0b << 32);
  pb[idx] = (ull)p1a | ((ull)p1b << 32);
}

// ---- pre-pack Wout into 2 fp16 planes, B-fragment order (round-13 exact) ------
__global__ void k_bpack(const float* __restrict__ W){
  unsigned idx = blockIdx.x*256 + threadIdx.x;   // 4,096,000
  unsigned lane = idx & 31, frag = idx >> 5;
  unsigned ktg = frag & 63, ng = frag >> 6;
  int k0 = ktg*16 + (lane&3)*2;
  int n  = ng*8 + (lane>>2);
  float w00 = W[(size_t)k0*V_ + n];
  float w01 = W[(size_t)(k0+1)*V_ + n];
  float w10 = W[(size_t)(k0+8)*V_ + n];
  float w11 = W[(size_t)(k0+9)*V_ + n];
  __half h00=__float2half_rn(w00), h01=__float2half_rn(w01);
  __half h10=__float2half_rn(w10), h11=__float2half_rn(w11);
  __half q00=__float2half_rn(w00-__half2float(h00));
  __half q01=__float2half_rn(w01-__half2float(h01));
  __half q10=__float2half_rn(w10-__half2float(h10));
  __half q11=__float2half_rn(w11-__half2float(h11));
  unsigned p0a = (unsigned)__half_as_ushort(h00) | ((unsigned)__half_as_ushort(h01)<<16);
  unsigned p0b = (unsigned)__half_as_ushort(h10) | ((unsigned)__half_as_ushort(h11)<<16);
  unsigned p1a = (unsigned)__half_as_ushort(q00) | ((unsigned)__half_as_ushort(q01)<<16);
  unsigned p1b = (unsigned)__half_as_ushort(q10) | ((unsigned)__half_as_ushort(q11)<<16);
  d_wp0[(size_t)frag*32 + lane] = (ull)p0a | ((ull)p0b << 32);
  d_wp1[(size_t)frag*32 + lane] = (ull)p1a | ((ull)p1b << 32);
}

// ------- LSTM GEMM via mma.sync fp16x2: gates[64,4096] partials ---------------
// grid = 32 col-tiles x 4 K-splits (=128); 256 threads (8 warps x 2 ng).
// D1 = [a0;a1] x b0 (8 mt), D2 = a0 x b1 (4 mt); out = D1[lo]+D1[hi]+D2.
__global__ void __launch_bounds__(256, 1) k_lstm_mma(
    const unsigned short* __restrict__ af, int nktg, int nkt,
    const ull* __restrict__ wba, const ull* __restrict__ wbb,
    float* __restrict__ gp)
{
  __shared__ unsigned short sA[2][512*8];   // 2 stages x 8KB (2 ktg each)
  const unsigned smb = su32(&sA[0][0]);
  const int tid = threadIdx.x, wid = tid >> 5, lane = tid & 31;
  const int ct = blockIdx.x & 31, sp = blockIdx.x >> 5;
  const int ktg0 = sp * nkt;
  const int nch = nkt >> 1;
  const int ng0 = ct*16 + wid*2;

#define FILL(s, c) {                                                         \
    _Pragma("unroll")                                                        \
    for (int i=0;i<2;i++){                                                   \
      int u = i*256 + tid;                                                   \
      int f = u >> 5, lh = u & 31;                                           \
      int mt = f >> 1, ktl = f & 1;                                          \
      size_t so = (((size_t)(mt*nktg + ktg0 + (c)*2 + ktl))*32 + lh)*16;     \
      cpa16(smb + (s)*8192 + u*16, (const char*)af + so);                    \
    }                                                                        \
    cp_commit(); }

  float D1[8][2][4], D2[4][2][4];
#pragma unroll
  for (int mt=0;mt<8;mt++)
#pragma unroll
    for (int nt=0;nt<2;nt++){ D1[mt][nt][0]=0.f;D1[mt][nt][1]=0.f;D1[mt][nt][2]=0.f;D1[mt][nt][3]=0.f; }
#pragma unroll
  for (int mt=0;mt<4;mt++)
#pragma unroll
    for (int nt=0;nt<2;nt++){ D2[mt][nt][0]=0.f;D2[mt][nt][1]=0.f;D2[mt][nt][2]=0.f;D2[mt][nt][3]=0.f; }

  FILL(0, 0)
  FILL(1, 1)

  for (int c = 0; c < nch; c++){
    if (c < nch-1) cp_wait1(); else cp_wait0();
    __syncthreads();
    const unsigned short* smA = &sA[c&1][0];
#pragma unroll
    for (int ktl = 0; ktl < 2; ktl++){
      int ktg = ktg0 + c*2 + ktl;
      unsigned b0[2][2], b1[2][2];
#pragma unroll
      for (int nt=0; nt<2; nt++){
        size_t bi = ((size_t)(ng0+nt)*nktg + ktg)*32 + lane;
        ull v0 = wba[bi], v1 = wbb[bi];
        b0[nt][0]=(unsigned)v0; b0[nt][1]=(unsigned)(v0>>32);
        b1[nt][0]=(unsigned)v1; b1[nt][1]=(unsigned)(v1>>32);
      }
#pragma unroll
      for (int mt=0; mt<4; mt++){
        uint4 av = *(const uint4*)(smA + (size_t)(mt*2+ktl)*256 + lane*8);
        unsigned a[4] = {av.x, av.y, av.z, av.w};
#pragma unroll
        for (int nt=0;nt<2;nt++){
          mma16816(D1[mt][nt], a, b0[nt]);
          mma16816(D2[mt][nt], a, b1[nt]);
        }
      }
#pragma unroll
      for (int mt=4; mt<8; mt++){
        uint4 av = *(const uint4*)(smA + (size_t)(mt*2+ktl)*256 + lane*8);
        unsigned a[4] = {av.x, av.y, av.z, av.w};
#pragma unroll
        for (int nt=0;nt<2;nt++) mma16816(D1[mt][nt], a, b0[nt]);
      }
    }
    __syncthreads();
    if (c+2 < nch){ FILL((c&1), c+2) }
  }
#undef FILL

  float* gps = gp + (size_t)sp*ROWS_*4096;
#pragma unroll
  for (int mt=0; mt<4; mt++)
#pragma unroll
    for (int nt=0; nt<2; nt++)
#pragma unroll
      for (int e=0; e<4; e++){
        int r = mt*16 + (lane>>2) + ((e>>1)<<3);
        int col = (ng0+nt)*8 + (lane&3)*2 + (e&1);
        gps[(size_t)r*4096 + col] = D1[mt][nt][e] + D1[mt+4][nt][e] + D2[mt][nt][e];
      }
}

// ------- bias + LSTM activation; writes h A-fragments --------------------------
__global__ void __launch_bounds__(512) k_act(const float* __restrict__ b,
    float* __restrict__ c,
    unsigned short* __restrict__ f1, int nk1, int kof1,
    unsigned short* __restrict__ f2, int nk2, int kof2)
{
  int idx = blockIdx.x*512 + threadIdx.x;      // 65536
  int h = idx & 1023, r = idx >> 10;
  size_t base = (size_t)r*4096;
  float gi = b[h], gf = b[1024+h], gg = b[2048+h], go = b[3072+h];
#pragma unroll
  for (int s = 0; s < 4; s++){
    const float* g = d_gp[s] + base;
    gi += g[h]; gf += g[1024+h]; gg += g[2048+h]; go += g[3072+h];
  }
  float cv = c[(size_t)r*1024 + h];
  float cn = sigmoid_(gf)*cv + sigmoid_(gi)*tanh_xla(gg);
  c[(size_t)r*1024 + h] = cn;
  float hn = sigmoid_(go)*tanh_xla(cn);
  wfrag(f1, nk1, r, kof1 + h, hn);
  if (f2) wfrag(f2, nk2, r, kof2 + h, hn);
}

// ------- mma.sync fp16x2 logits GEMM + softmax partials + Gumbel argmax --------
// grid 125 CTAs (one 128-col tile), 256 threads. A = h1 frags (d_af1 ktg 64..127).
__global__ void __launch_bounds__(256, 1) k_logits_mma(int t,
     const float* __restrict__ bout)
{
  extern __shared__ char smem[];
  const unsigned smb = su32(smem);
  const int tid = threadIdx.x, wid = tid >> 5, lane = tid & 31;
  const int cb = blockIdx.x;
  const int ng0 = cb*16 + wid*2;

  float* LG = (float*)(smem + 32768);    // [64][136]

#define FILL_A(s, ck) {                                                      \
    unsigned dst = smb + (s)*16384;                                          \
    const char* src = (const char*)d_af1;                                    \
    _Pragma("unroll")                                                        \
    for (int i=0;i<4;i++){                                                   \
      int u = i*256 + tid;                                                   \
      int f = u >> 5, lh = u & 31;                                           \
      int mt = f >> 2, ktl = f & 3;                                          \
      size_t so = (((size_t)(mt*NKT1_ + 64 + (ck)*4 + ktl))*32 + lh)*16;     \
      cpa16(dst + u*16, src + so);                                           \
    }                                                                        \
    cp_commit(); }

  float D1[8][2][4], D2[4][2][4];
#pragma unroll
  for (int mt=0;mt<8;mt++)
#pragma unroll
    for (int nt=0;nt<2;nt++){ D1[mt][nt][0]=0.f;D1[mt][nt][1]=0.f;D1[mt][nt][2]=0.f;D1[mt][nt][3]=0.f; }
#pragma unroll
  for (int mt=0;mt<4;mt++)
#pragma unroll
    for (int nt=0;nt<2;nt++){ D2[mt][nt][0]=0.f;D2[mt][nt][1]=0.f;D2[mt][nt][2]=0.f;D2[mt][nt][3]=0.f; }

  FILL_A(0, 0)
  FILL_A(1, 1)

  for (int c = 0; c < 16; c++){
    if (c < 15) cp_wait1(); else cp_wait0();
    __syncthreads();
    const unsigned short* smA = (const unsigned short*)(smem + (c&1)*16384);
#pragma unroll
    for (int ktl = 0; ktl < 4; ktl++){
      int ktg = c*4 + ktl;
      unsigned b0[2][2], b1[2][2];
#pragma unroll
      for (int nt=0; nt<2; nt++){
        size_t bi = ((size_t)((ng0+nt)*64 + ktg))*32 + lane;
        ull v0 = d_wp0[bi], v1 = d_wp1[bi];
        b0[nt][0]=(unsigned)v0; b0[nt][1]=(unsigned)(v0>>32);
        b1[nt][0]=(unsigned)v1; b1[nt][1]=(unsigned)(v1>>32);
      }
#pragma unroll
      for (int mt=0; mt<4; mt++){
        uint4 av = *(const uint4*)(smA + (size_t)(mt*4+ktl)*256 + lane*8);
        unsigned a[4] = {av.x, av.y, av.z, av.w};
#pragma unroll
        for (int nt=0;nt<2;nt++){
          mma16816(D1[mt][nt], a, b0[nt]);
          mma16816(D2[mt][nt], a, b1[nt]);
        }
      }
#pragma unroll
      for (int mt=4; mt<8; mt++){
        uint4 av = *(const uint4*)(smA + (size_t)(mt*4+ktl)*256 + lane*8);
        unsigned a[4] = {av.x, av.y, av.z, av.w};
#pragma unroll
        for (int nt=0;nt<2;nt++) mma16816(D1[mt][nt], a, b0[nt]);
      }
    }
    __syncthreads();
    if (c+2 < 16){ FILL_A((c&1), c+2) }
  }
#undef FILL_A

  // combine into LG[64][136]: out = D1[a0 rows] + D1[a1 rows] + D2
#pragma unroll
  for (int mt=0; mt<4; mt++)
#pragma unroll
    for (int nt=0; nt<2; nt++)
#pragma unroll
      for (int e=0; e<4; e++){
        int row = mt*16 + (lane>>2) + ((e>>1)<<3);
        int col = wid*16 + nt*8 + (lane&3)*2 + (e&1);
        LG[row*136 + col] = D1[mt][nt][e] + D1[mt+4][nt][e] + D2[mt][nt][e];
      }
  __syncthreads();

  // bias + per-tile softmax partials + Gumbel argmax (row = tid/4, 32 cols each)
  unsigned k0p[2], k1p[2];
  { unsigned a0,a1; tf2x32(0u,42u,0u,0u,a0,a1); tf2x32(a0,a1,0u,(unsigned)t,k0p[0],k1p[0]); }
  { unsigned a0,a1; tf2x32(0u,42u,0u,1u,a0,a1); tf2x32(a0,a1,0u,(unsigned)t,k0p[1],k1p[1]); }

  const int row = tid >> 2, q = tid & 3;
  const int pass = row >> 5, bb = row & 31;
  float m = -INFINITY;
#pragma unroll 4
  for (int j=0;j<32;j++){
    int cl = q*32 + j;
    float v = LG[row*136 + cl] + bout[cb*128 + cl];
    LG[row*136 + cl] = v;
    m = fmaxf(m, v);
  }
  m = fmaxf(m, __shfl_xor_sync(0xffffffffu, m, 1));
  m = fmaxf(m, __shfl_xor_sync(0xffffffffu, m, 2));
  float s = 0.f, bv = -INFINITY; int bi = 0x7fffffff;
  for (int j=0;j<32;j++){
    int cl = q*32 + j, cgl = cb*128 + cl;
    float v = LG[row*136 + cl];
    s += __expf(v - m);
    float g = gumbel_from_bits(pbits(k0p[pass], k1p[pass], (unsigned)(bb*V_ + cgl)));
    float tv = v + g;
    if (tv > bv){ bv = tv; bi = cgl; }
  }
  s += __shfl_xor_sync(0xffffffffu, s, 1);
  s += __shfl_xor_sync(0xffffffffu, s, 2);
#pragma unroll
  for (int msk=1; msk<=2; msk<<=1){
    float ov = __shfl_xor_sync(0xffffffffu, bv, msk);
    int   oi = __shfl_xor_sync(0xffffffffu, bi, msk);
    if (ov > bv || (ov == bv && oi < bi)){ bv = ov; bi = oi; }
  }
  if (q == 0){
    d_pmax[row*NTIL_+cb] = m; d_psum[row*NTIL_+cb] = s;
    d_amv [row*NTIL_+cb] = bv; d_ami [row*NTIL_+cb] = bi;
  }
  __syncthreads();

  // coalesced logits store
#pragma unroll
  for (int i=0;i<8;i++){
    int e2 = i*256 + tid;
    int rr = e2 >> 5, c4 = (e2 & 31) * 4;
    float4 v = *(const float4*)&LG[rr*136 + c4];
    *(float4*)&d_logits[(size_t)rr*V_ + cb*128 + c4] = v;
  }
}

// ------- fused: row LSE + p write + argmax/token + next-step emb frags ---------
// grid 250 tiles of 64 cols; block 256. Blocks 0..63 also do row argmax + token.
__global__ void __launch_bounds__(256) k_final(int t, const int* __restrict__ x,
    const float* __restrict__ emb, float* __restrict__ out)
{
  __shared__ float tmpM[4][ROWS_], tmpS[4][ROWS_];
  __shared__ float sM[ROWS_], sL[ROWS_];
  __shared__ float sv[256];
  __shared__ int   si[256];
  __shared__ int   stok;
  const int tid = threadIdx.x, cb = blockIdx.x;

  // Phase A: per-row log-sum-exp over 125 tile partials (4 threads per row)
  {
    const int row = tid >> 2, part = tid & 3;
    const float* pm = d_pmax + (size_t)row*NTIL_;
    const float* ps = d_psum + (size_t)row*NTIL_;
    float m = -INFINITY;
    for (int j = part; j < NTIL_; j += 4) m = fmaxf(m, pm[j]);
    tmpM[part][row] = m;
    __syncthreads();
    float M = fmaxf(fmaxf(tmpM[0][row], tmpM[1][row]), fmaxf(tmpM[2][row], tmpM[3][row]));
    float s = 0.f;
    for (int j = part; j < NTIL_; j += 4) s += ps[j]*__expf(pm[j]-M);
    tmpS[part][row] = s;
    __syncthreads();
    if (part == 0){
      sM[row] = M;
      sL[row] = logf((tmpS[0][row]+tmpS[1][row]) + (tmpS[2][row]+tmpS[3][row]));
    }
    __syncthreads();
  }

  // Phase B: p = exp(logit - M - L) for this 64-col tile
  const int cbase = cb * 64;
#pragma unroll
  for (int i=0;i<4;i++){
    int e = i*256 + tid;
    int row = e >> 4, c4 = (e & 15) * 4;
    float ML = sM[row] + sL[row];
    float4 lg = *(const float4*)&d_logits[(size_t)row*V_ + cbase + c4];
    float4 pv = make_float4(__expf(lg.x-ML), __expf(lg.y-ML),
                            __expf(lg.z-ML), __expf(lg.w-ML));
    int pass = row>>5, b = row&31;
    size_t base = (pass==0) ? (size_t)O_PS + ((size_t)b*T_ + t)*V_
                            : (size_t)O_PF + ((size_t)b*T_ + t)*V_;
    *(float4*)&out[base + cbase + c4] = pv;
  }

  // Phase C (blocks 0..63): global argmax for row=cb, token, emb-frag gather
  if (cb < ROWS_){
    const int row = cb;
    float bv = -INFINITY; int bi = 0x7fffffff;
    for (int j=tid; j<NTIL_; j+=256){
      float v = d_amv[(size_t)row*NTIL_+j]; int ii = d_ami[(size_t)row*NTIL_+j];
      if (v > bv || (v == bv && ii < bi)){ bv = v; bi = ii; }
    }
    sv[tid] = bv; si[tid] = bi; __syncthreads();
    for (int k=128;k>0;k>>=1){
      if (tid<k){
        float ov = sv[tid+k]; int oi = si[tid+k];
        if (ov > sv[tid] || (ov == sv[tid] && oi < si[tid])){ sv[tid]=ov; si[tid]=oi; }
      }
      __syncthreads();
    }
    if (tid == 0){
      int idx = si[0];
      int pass = row>>5, b = row&31;
      if (pass == 0){ out[(size_t)b*T_ + t] = (float)idx; d_tok[b] = idx; stok = idx; }
      else          { out[(size_t)O_SF + (size_t)b*T_ + t] = (float)idx;
                      stok = x[(size_t)b*T_ + t]; }
    }
    __syncthreads();
    const int tok = stok;
    for (int k = tid; k < E_; k += 256)
      wfrag(d_af0, NKT0_, row, k, emb[(size_t)tok*E_ + k]);
  }
}

// ---------------- launch -------------------------------------------------------
extern "C" void kernel_launch(void* const* d_in, const int* in_sizes, int n_in,
                              void* d_out, int out_size)
{
  const int*   x    = (const int*)  d_in[0];
  const float* z    = (const float*)d_in[1];
  const float* emb  = (const float*)d_in[2];
  const float* Wx0  = (const float*)d_in[3];
  const float* Wh0  = (const float*)d_in[4];
  const float* b0   = (const float*)d_in[5];
  const float* Wx1  = (const float*)d_in[6];
  const float* Wh1  = (const float*)d_in[7];
  const float* b1   = (const float*)d_in[8];
  const float* Wout = (const float*)d_in[9];
  const float* bout = (const float*)d_in[10];
  float* out = (float*)d_out;

  float* pc0;  cudaGetSymbolAddress((void**)&pc0,  d_c0);
  float* pc1;  cudaGetSymbolAddress((void**)&pc1,  d_c1);
  float* pgp;  cudaGetSymbolAddress((void**)&pgp,  d_gp);
  unsigned short* paf0; cudaGetSymbolAddress((void**)&paf0, d_af0);
  unsigned short* paf1; cudaGetSymbolAddress((void**)&paf1, d_af1);
  ull* pwb0a; cudaGetSymbolAddress((void**)&pwb0a, d_wb0a);
  ull* pwb0b; cudaGetSymbolAddress((void**)&pwb0b, d_wb0b);
  ull* pwb1a; cudaGetSymbolAddress((void**)&pwb1a, d_wb1a);
  ull* pwb1b; cudaGetSymbolAddress((void**)&pwb1b, d_wb1b);

  const int SMEM_LG = 32768 + 64*136*4;   // 67584 bytes
  static int attr_set = 0;
  if (!attr_set){
    cudaFuncSetAttribute(k_logits_mma, cudaFuncAttributeMaxDynamicSharedMemorySize, SMEM_LG);
    attr_set = 1;
  }

  k_init <<<256, 256>>>();
  k_fillA<<<160, 256>>>(z, emb);
  k_wpack<<<6656, 256>>>(Wx0, 640,  Wh0, NKT0_, pwb0a, pwb0b);
  k_wpack<<<8192, 256>>>(Wx1, 1024, Wh1, NKT1_, pwb1a, pwb1b);
  k_bpack<<<16000, 256>>>(Wout);
  for (int t = 0; t < T_; t++){
    k_lstm_mma<<<128, 256>>>(paf0, NKT0_, 26, pwb0a, pwb0b, pgp);
    k_act <<<128, 512>>>(b0, pc0, paf0, NKT0_, 640, paf1, NKT1_, 0);
    k_lstm_mma<<<128, 256>>>(paf1, NKT1_, 32, pwb1a, pwb1b, pgp);
    k_act <<<128, 512>>>(b1, pc1, paf1, NKT1_, 1024, (unsigned short*)nullptr, 0, 0);
    k_logits_mma<<<NTIL_, 256, SMEM_LG>>>(t, bout);
    k_final<<<250, 256>>>(t, x, emb, out);
  }
}